// round 8
// baseline (speedup 1.0000x reference)
#include <cuda_runtime.h>
#include <cuda_fp16.h>
#include <cstdint>

#define HID  256
#define QN   200
#define NPIX (256 * 256)
#define NB   4
#define NROW (NB * QN)    // 800 merged (b,q) rows

#define MROWS   13        // ceil(200/16) query row-tiles of 16
#define KSTEPS  16        // 256 / 16
#define PTILE   64        // pixels per GEMM CTA
#define BSTRIDE 132       // smem row stride in u32 (k-pairs), read-conflict-free
#define NWARP   7         // 7 warps x 2 m-tiles (warp base 6 -> tile 12 only)
#define GTHREADS (NWARP * 32)

// ---------------------------------------------------------------------------
// Device scratch (allocation-free)
// ---------------------------------------------------------------------------
__device__ float g_h [NROW * HID];                          // hidden fp32
__device__ float g_me[NROW * HID];                          // mask_embed fp32
__device__ uint4 g_AH[NB * MROWS * KSTEPS * 32];            // A fragments (fp16)

// ---------------------------------------------------------------------------
// mma.sync m16n8k16 fp16 in / fp32 accum (baseline PTX, valid on sm_100)
// ---------------------------------------------------------------------------
__device__ __forceinline__ void mma_f16(float* d, uint4 a, uint32_t b0, uint32_t b1) {
    asm volatile(
        "mma.sync.aligned.m16n8k16.row.col.f32.f16.f16.f32 "
        "{%0,%1,%2,%3}, {%4,%5,%6,%7}, {%8,%9}, {%0,%1,%2,%3};"
        : "+f"(d[0]), "+f"(d[1]), "+f"(d[2]), "+f"(d[3])
        : "r"(a.x), "r"(a.y), "r"(a.z), "r"(a.w), "r"(b0), "r"(b1));
}

__device__ __forceinline__ uint32_t pack_f16(float a, float b) {
    __half2 h = __floats2half2_rn(a, b);
    return *reinterpret_cast<uint32_t*>(&h);
}

// ---------------------------------------------------------------------------
// MLP layer kernel: C[r, n] = act( sum_k A[r,k] * W[n,k] + bias[n] )
// 32x32 tile, 128 threads, coalesced smem staging.
// grid = (NROW/32 = 25, HID/32 = 8)
// ---------------------------------------------------------------------------
template<bool RELU>
__global__ __launch_bounds__(128) void layer_kernel(
    const float* __restrict__ A, const float* __restrict__ W,
    const float* __restrict__ bias, float* __restrict__ C)
{
    __shared__ float sA[16][32];   // [k][row]
    __shared__ float sW[16][32];   // [k][col]

    const int tid = threadIdx.x;
    const int r0 = blockIdx.x * 32;
    const int n0 = blockIdx.y * 32;
    const int tr = tid & 7;        // row group: 4 rows
    const int tc = tid >> 3;       // col group: 2 cols (0..15)
    const int lrow = tid >> 2;     // 0..31: load row
    const int lj   = (tid & 3) * 4;

    float acc[4][2] = {};

    for (int kc = 0; kc < HID; kc += 16) {
        __syncthreads();
        float4 va = *reinterpret_cast<const float4*>(A + (size_t)(r0 + lrow) * HID + kc + lj);
        sA[lj+0][lrow] = va.x; sA[lj+1][lrow] = va.y;
        sA[lj+2][lrow] = va.z; sA[lj+3][lrow] = va.w;
        float4 vw = *reinterpret_cast<const float4*>(W + (size_t)(n0 + lrow) * HID + kc + lj);
        sW[lj+0][lrow] = vw.x; sW[lj+1][lrow] = vw.y;
        sW[lj+2][lrow] = vw.z; sW[lj+3][lrow] = vw.w;
        __syncthreads();

        #pragma unroll
        for (int k = 0; k < 16; k++) {
            float4 a = *reinterpret_cast<const float4*>(&sA[k][tr * 4]);
            float2 w = *reinterpret_cast<const float2*>(&sW[k][tc * 2]);
            acc[0][0] = fmaf(a.x, w.x, acc[0][0]); acc[0][1] = fmaf(a.x, w.y, acc[0][1]);
            acc[1][0] = fmaf(a.y, w.x, acc[1][0]); acc[1][1] = fmaf(a.y, w.y, acc[1][1]);
            acc[2][0] = fmaf(a.z, w.x, acc[2][0]); acc[2][1] = fmaf(a.z, w.y, acc[2][1]);
            acc[3][0] = fmaf(a.w, w.x, acc[3][0]); acc[3][1] = fmaf(a.w, w.y, acc[3][1]);
        }
    }

    const float b0 = bias[n0 + tc * 2];
    const float b1 = bias[n0 + tc * 2 + 1];
    #pragma unroll
    for (int r = 0; r < 4; r++) {
        float v0 = acc[r][0] + b0;
        float v1 = acc[r][1] + b1;
        if (RELU) { v0 = v0 > 0.f ? v0 : 0.f; v1 = v1 > 0.f ? v1 : 0.f; }
        *reinterpret_cast<float2*>(C + (size_t)(r0 + tr * 4 + r) * HID + n0 + tc * 2)
            = make_float2(v0, v1);
    }
}

// ---------------------------------------------------------------------------
// Pack mask_embed into per-lane A fragments (single fp16 rounding).
// A frag (m16n8k16): lane t (g=t/4, i=t%4) holds rows {mr*16+g, +8},
// cols {ks*16+2i, +1, +8, +9}.
// ---------------------------------------------------------------------------
__global__ __launch_bounds__(512) void pack_kernel()
{
    const int blk = blockIdx.x;              // b*MROWS + mr
    const int b   = blk / MROWS;
    const int mr  = blk % MROWS;
    const int ks  = threadIdx.x >> 5;        // 0..15
    const int lane = threadIdx.x & 31;
    const int g = lane >> 2, i4 = lane & 3;

    const int r0 = mr * 16 + g;
    const int r1 = r0 + 8;
    const int c0 = ks * 16 + i4 * 2;

    float v[2][4];
    #pragma unroll
    for (int rr = 0; rr < 2; rr++) {
        const int r = rr ? r1 : r0;
        #pragma unroll
        for (int cc = 0; cc < 4; cc++) {
            const int c = c0 + (cc >> 1) * 8 + (cc & 1);
            v[rr][cc] = (r < QN) ? g_me[(size_t)(b * QN + r) * HID + c] : 0.f;
        }
    }

    uint4 ah;
    ah.x = pack_f16(v[0][0], v[0][1]);
    ah.y = pack_f16(v[1][0], v[1][1]);
    ah.z = pack_f16(v[0][2], v[0][3]);
    ah.w = pack_f16(v[1][2], v[1][3]);

    g_AH[((size_t)(b * MROWS + mr) * KSTEPS + ks) * 32 + lane] = ah;
}

// ---------------------------------------------------------------------------
// GEMM: out[b,q,p] = sum_c me[b,q,c] * mf[b,c,p]
// CTA = 64-pixel stripe x all query rows (mf read exactly once).
// 7 warps, 2 m-tiles each (halves B smem re-reads: 1 LDS per MMA),
// role rotated by blockIdx.x. B fp16 in smem [pixel][kpair], stride 132.
// ---------------------------------------------------------------------------
__global__ __launch_bounds__(GTHREADS) void gemm_kernel(
    const float* __restrict__ mf, float* __restrict__ out)
{
    extern __shared__ uint32_t sB[];               // [64 pixels][BSTRIDE kpairs]

    const int tid  = threadIdx.x;
    const int lane = tid & 31;
    const int w    = tid >> 5;
    const int g    = lane >> 2, i4 = lane & 3;

    const int p0 = blockIdx.x * PTILE;
    const int b  = blockIdx.y;

    const float* mfb  = mf  + (size_t)b * HID * NPIX;
    float*       outb = out + (size_t)b * QN  * NPIX;

    // ---- load + convert B tile: 64 pixels x 256 channels, fp32 -> fp16 ----
    for (int idx = tid; idx < 128 * 16; idx += GTHREADS) {
        const int cp  = idx >> 4;
        const int p4  = idx & 15;
        const float* r0 = mfb + (size_t)(2 * cp)     * NPIX + p0 + p4 * 4;
        const float* r1 = mfb + (size_t)(2 * cp + 1) * NPIX + p0 + p4 * 4;
        float4 v0 = *reinterpret_cast<const float4*>(r0);
        float4 v1 = *reinterpret_cast<const float4*>(r1);
        const float a0[4] = {v0.x, v0.y, v0.z, v0.w};
        const float a1[4] = {v1.x, v1.y, v1.z, v1.w};
        #pragma unroll
        for (int s = 0; s < 4; s++) {
            const int j = (s + p4) & 3;            // stagger -> fewer store conflicts
            sB[(uint32_t)(p4 * 4 + j) * BSTRIDE + cp] = pack_f16(a0[j], a1[j]);
        }
    }
    __syncthreads();

    // ---- compute: warp base rotated for balance; m-tiles {2b, 2b+1} ----
    const int base = (w + (int)blockIdx.x) % NWARP;
    const int mr0  = 2 * base;
    const int mr1  = 2 * base + 1;
    const bool has1 = (mr1 < MROWS);               // base 6 -> tile 12 only

    float acc0[8][4];
    float acc1[8][4];
    #pragma unroll
    for (int n = 0; n < 8; n++)
        #pragma unroll
        for (int x = 0; x < 4; x++) { acc0[n][x] = 0.f; acc1[n][x] = 0.f; }

    const uint4* pAH0 = g_AH + ((size_t)(b * MROWS + mr0) * KSTEPS) * 32 + lane;
    const uint4* pAH1 = g_AH + ((size_t)(b * MROWS + (has1 ? mr1 : mr0)) * KSTEPS) * 32 + lane;

    #pragma unroll 4
    for (int ks = 0; ks < KSTEPS; ks++) {
        const uint4 ah0 = pAH0[ks * 32];
        uint4 ah1;
        if (has1) ah1 = pAH1[ks * 32];
        const uint32_t cb = (uint32_t)(ks * 8 + i4);
        #pragma unroll
        for (int nc = 0; nc < 8; nc++) {
            const uint32_t rb = (uint32_t)(nc * 8 + g) * BSTRIDE;
            const uint32_t b0 = sB[rb + cb];
            const uint32_t b1 = sB[rb + cb + 4];
            mma_f16(acc0[nc], ah0, b0, b1);
            if (has1) mma_f16(acc1[nc], ah1, b0, b1);
        }
    }

    // ---- epilogue: D frag (16x8) rows = queries, cols = pixel pairs ----
    {
        const int q = mr0 * 16 + g;
        if (q < QN) {
            float* o = outb + (size_t)q * NPIX + p0 + i4 * 2;
            #pragma unroll
            for (int nc = 0; nc < 8; nc++)
                *reinterpret_cast<float2*>(o + nc * 8) = make_float2(acc0[nc][0], acc0[nc][1]);
        }
        const int q2 = q + 8;
        if (q2 < QN) {
            float* o2 = outb + (size_t)q2 * NPIX + p0 + i4 * 2;
            #pragma unroll
            for (int nc = 0; nc < 8; nc++)
                *reinterpret_cast<float2*>(o2 + nc * 8) = make_float2(acc0[nc][2], acc0[nc][3]);
        }
    }
    if (has1) {
        const int q = mr1 * 16 + g;
        if (q < QN) {
            float* o = outb + (size_t)q * NPIX + p0 + i4 * 2;
            #pragma unroll
            for (int nc = 0; nc < 8; nc++)
                *reinterpret_cast<float2*>(o + nc * 8) = make_float2(acc1[nc][0], acc1[nc][1]);
        }
        const int q2 = q + 8;
        if (q2 < QN) {
            float* o2 = outb + (size_t)q2 * NPIX + p0 + i4 * 2;
            #pragma unroll
            for (int nc = 0; nc < 8; nc++)
                *reinterpret_cast<float2*>(o2 + nc * 8) = make_float2(acc1[nc][2], acc1[nc][3]);
        }
    }
}

// ---------------------------------------------------------------------------
extern "C" void kernel_launch(void* const* d_in, const int* in_sizes, int n_in,
                              void* d_out, int out_size)
{
    const float* queries = (const float*)d_in[0];  // (4, 200, 256)
    const float* mf      = (const float*)d_in[1];  // (4, 256, 256, 256)
    const float* w1      = (const float*)d_in[2];
    const float* b1      = (const float*)d_in[3];
    const float* w2      = (const float*)d_in[4];
    const float* b2      = (const float*)d_in[5];
    float* out = (float*)d_out;                    // (4, 200, 256, 256)

    float* hbuf;  cudaGetSymbolAddress((void**)&hbuf,  g_h);
    float* mebuf; cudaGetSymbolAddress((void**)&mebuf, g_me);

    const int smem = PTILE * BSTRIDE * (int)sizeof(uint32_t);   // 33792 B
    cudaFuncSetAttribute(gemm_kernel, cudaFuncAttributeMaxDynamicSharedMemorySize, smem);

    layer_kernel<true ><<<dim3(NROW / 32, HID / 32), 128>>>(queries, w1, b1, hbuf);
    layer_kernel<false><<<dim3(NROW / 32, HID / 32), 128>>>(hbuf,    w2, b2, mebuf);
    pack_kernel<<<NB * MROWS, 512>>>();
    gemm_kernel<<<dim3(NPIX / PTILE, NB), GTHREADS, smem>>>(mf, out);
}

// round 9
// speedup vs baseline: 1.3072x; 1.3072x over previous
#include <cuda_runtime.h>
#include <cuda_fp16.h>
#include <cstdint>

#define HID  256
#define QN   200
#define NPIX (256 * 256)
#define NB   4
#define NROW (NB * QN)    // 800 merged (b,q) rows

#define MROWS   13        // ceil(200/16) query row-tiles of 16
#define KSTEPS  16        // 256 / 16
#define PTILE   64        // pixels per GEMM CTA
#define BSTRIDE 132       // smem row stride in u32 (k-pairs), read-conflict-free
#define NWARP   13        // 13 warps: 12 dual-m-tile warps + 1 single
#define GTHREADS (NWARP * 32)

// ---------------------------------------------------------------------------
// Device scratch (allocation-free)
// ---------------------------------------------------------------------------
__device__ float g_h [NROW * HID];                          // hidden fp32
__device__ float g_me[NROW * HID];                          // mask_embed fp32
__device__ uint4 g_AH[NB * MROWS * KSTEPS * 32];            // A fragments (fp16)

// ---------------------------------------------------------------------------
// mma.sync m16n8k16 fp16 in / fp32 accum (baseline PTX, valid on sm_100)
// ---------------------------------------------------------------------------
__device__ __forceinline__ void mma_f16(float* d, uint4 a, uint32_t b0, uint32_t b1) {
    asm volatile(
        "mma.sync.aligned.m16n8k16.row.col.f32.f16.f16.f32 "
        "{%0,%1,%2,%3}, {%4,%5,%6,%7}, {%8,%9}, {%0,%1,%2,%3};"
        : "+f"(d[0]), "+f"(d[1]), "+f"(d[2]), "+f"(d[3])
        : "r"(a.x), "r"(a.y), "r"(a.z), "r"(a.w), "r"(b0), "r"(b1));
}

__device__ __forceinline__ uint32_t pack_f16(float a, float b) {
    __half2 h = __floats2half2_rn(a, b);
    return *reinterpret_cast<uint32_t*>(&h);
}

// ---------------------------------------------------------------------------
// MLP layer kernel: C[r, n] = act( sum_k A[r,k] * W[n,k] + bias[n] )
// 32x32 tile, 128 threads, coalesced smem staging.
// grid = (NROW/32 = 25, HID/32 = 8)
// ---------------------------------------------------------------------------
template<bool RELU>
__global__ __launch_bounds__(128) void layer_kernel(
    const float* __restrict__ A, const float* __restrict__ W,
    const float* __restrict__ bias, float* __restrict__ C)
{
    __shared__ float sA[16][32];   // [k][row]
    __shared__ float sW[16][32];   // [k][col]

    const int tid = threadIdx.x;
    const int r0 = blockIdx.x * 32;
    const int n0 = blockIdx.y * 32;
    const int tr = tid & 7;        // row group: 4 rows
    const int tc = tid >> 3;       // col group: 2 cols (0..15)
    const int lrow = tid >> 2;     // 0..31: load row
    const int lj   = (tid & 3) * 4;

    float acc[4][2] = {};

    for (int kc = 0; kc < HID; kc += 16) {
        __syncthreads();
        float4 va = *reinterpret_cast<const float4*>(A + (size_t)(r0 + lrow) * HID + kc + lj);
        sA[lj+0][lrow] = va.x; sA[lj+1][lrow] = va.y;
        sA[lj+2][lrow] = va.z; sA[lj+3][lrow] = va.w;
        float4 vw = *reinterpret_cast<const float4*>(W + (size_t)(n0 + lrow) * HID + kc + lj);
        sW[lj+0][lrow] = vw.x; sW[lj+1][lrow] = vw.y;
        sW[lj+2][lrow] = vw.z; sW[lj+3][lrow] = vw.w;
        __syncthreads();

        #pragma unroll
        for (int k = 0; k < 16; k++) {
            float4 a = *reinterpret_cast<const float4*>(&sA[k][tr * 4]);
            float2 w = *reinterpret_cast<const float2*>(&sW[k][tc * 2]);
            acc[0][0] = fmaf(a.x, w.x, acc[0][0]); acc[0][1] = fmaf(a.x, w.y, acc[0][1]);
            acc[1][0] = fmaf(a.y, w.x, acc[1][0]); acc[1][1] = fmaf(a.y, w.y, acc[1][1]);
            acc[2][0] = fmaf(a.z, w.x, acc[2][0]); acc[2][1] = fmaf(a.z, w.y, acc[2][1]);
            acc[3][0] = fmaf(a.w, w.x, acc[3][0]); acc[3][1] = fmaf(a.w, w.y, acc[3][1]);
        }
    }

    const float b0 = bias[n0 + tc * 2];
    const float b1 = bias[n0 + tc * 2 + 1];
    #pragma unroll
    for (int r = 0; r < 4; r++) {
        float v0 = acc[r][0] + b0;
        float v1 = acc[r][1] + b1;
        if (RELU) { v0 = v0 > 0.f ? v0 : 0.f; v1 = v1 > 0.f ? v1 : 0.f; }
        *reinterpret_cast<float2*>(C + (size_t)(r0 + tr * 4 + r) * HID + n0 + tc * 2)
            = make_float2(v0, v1);
    }
}

// ---------------------------------------------------------------------------
// Pack mask_embed into per-lane A fragments (single fp16 rounding).
// A frag (m16n8k16): lane t (g=t/4, i=t%4) holds rows {mr*16+g, +8},
// cols {ks*16+2i, +1, +8, +9}.
// ---------------------------------------------------------------------------
__global__ __launch_bounds__(512) void pack_kernel()
{
    const int blk = blockIdx.x;              // b*MROWS + mr
    const int b   = blk / MROWS;
    const int mr  = blk % MROWS;
    const int ks  = threadIdx.x >> 5;        // 0..15
    const int lane = threadIdx.x & 31;
    const int g = lane >> 2, i4 = lane & 3;

    const int r0 = mr * 16 + g;
    const int r1 = r0 + 8;
    const int c0 = ks * 16 + i4 * 2;

    float v[2][4];
    #pragma unroll
    for (int rr = 0; rr < 2; rr++) {
        const int r = rr ? r1 : r0;
        #pragma unroll
        for (int cc = 0; cc < 4; cc++) {
            const int c = c0 + (cc >> 1) * 8 + (cc & 1);
            v[rr][cc] = (r < QN) ? g_me[(size_t)(b * QN + r) * HID + c] : 0.f;
        }
    }

    uint4 ah;
    ah.x = pack_f16(v[0][0], v[0][1]);
    ah.y = pack_f16(v[1][0], v[1][1]);
    ah.z = pack_f16(v[0][2], v[0][3]);
    ah.w = pack_f16(v[1][2], v[1][3]);

    g_AH[((size_t)(b * MROWS + mr) * KSTEPS + ks) * 32 + lane] = ah;
}

// ---------------------------------------------------------------------------
// GEMM: out[b,q,p] = sum_c me[b,q,c] * mf[b,c,p]
// CTA = 64-pixel stripe x all query rows (mf read exactly once).
// 13 warps (R7 occupancy) with R8's register reuse:
//   warps 0..11: m-pair (2p, 2p+1) x 4 n-chunks  -> each B frag feeds 2 MMAs
//   warp  12   : m-tile 12 x all 8 n-chunks
// Perfectly balanced: 128 MMAs per warp. Roles rotated by blockIdx.x.
// ---------------------------------------------------------------------------
__global__ __launch_bounds__(GTHREADS) void gemm_kernel(
    const float* __restrict__ mf, float* __restrict__ out)
{
    extern __shared__ uint32_t sB[];               // [64 pixels][BSTRIDE kpairs]

    const int tid  = threadIdx.x;
    const int lane = tid & 31;
    const int w    = tid >> 5;
    const int g    = lane >> 2, i4 = lane & 3;

    const int p0 = blockIdx.x * PTILE;
    const int b  = blockIdx.y;

    const float* mfb  = mf  + (size_t)b * HID * NPIX;
    float*       outb = out + (size_t)b * QN  * NPIX;

    // ---- load + convert B tile: 64 pixels x 256 channels, fp32 -> fp16 ----
    for (int idx = tid; idx < 128 * 16; idx += GTHREADS) {
        const int cp  = idx >> 4;
        const int p4  = idx & 15;
        const float* r0 = mfb + (size_t)(2 * cp)     * NPIX + p0 + p4 * 4;
        const float* r1 = mfb + (size_t)(2 * cp + 1) * NPIX + p0 + p4 * 4;
        float4 v0 = *reinterpret_cast<const float4*>(r0);
        float4 v1 = *reinterpret_cast<const float4*>(r1);
        const float a0[4] = {v0.x, v0.y, v0.z, v0.w};
        const float a1[4] = {v1.x, v1.y, v1.z, v1.w};
        #pragma unroll
        for (int s = 0; s < 4; s++) {
            const int j = (s + p4) & 3;            // stagger -> fewer store conflicts
            sB[(uint32_t)(p4 * 4 + j) * BSTRIDE + cp] = pack_f16(a0[j], a1[j]);
        }
    }
    __syncthreads();

    // ---- role assignment (rotated across CTAs for SMSP balance) ----
    const int wr   = (w + (int)blockIdx.x) % NWARP;
    const bool dual = (wr < 12);
    const int mr0  = dual ? 2 * (wr >> 1) : 12;
    const int mr1  = mr0 + 1;                       // valid only if dual
    const int ncb  = dual ? (wr & 1) * 4 : 0;       // n-chunk base

    // dual: acc0 = tile mr0 (nc ncb..ncb+3), acc1 = tile mr1 (same ncs)
    // single: acc0 = tile 12 nc 0..3, acc1 = tile 12 nc 4..7
    float acc0[4][4] = {};
    float acc1[4][4] = {};

    const uint4* pAH0 = g_AH + ((size_t)(b * MROWS + mr0) * KSTEPS) * 32 + lane;
    const uint4* pAH1 = g_AH + ((size_t)(b * MROWS + (dual ? mr1 : mr0)) * KSTEPS) * 32 + lane;

    #pragma unroll 4
    for (int ks = 0; ks < KSTEPS; ks++) {
        const uint4 ah0 = pAH0[ks * 32];
        uint4 ah1;
        if (dual) ah1 = pAH1[ks * 32];
        const uint32_t cb = (uint32_t)(ks * 8 + i4);
        #pragma unroll
        for (int j = 0; j < 4; j++) {
            const uint32_t rb0 = (uint32_t)((ncb + j) * 8 + g) * BSTRIDE;
            const uint32_t b00 = sB[rb0 + cb];
            const uint32_t b01 = sB[rb0 + cb + 4];
            mma_f16(acc0[j], ah0, b00, b01);
            if (dual) {
                mma_f16(acc1[j], ah1, b00, b01);
            } else {
                const uint32_t rb1 = (uint32_t)((j + 4) * 8 + g) * BSTRIDE;
                mma_f16(acc1[j], ah0, sB[rb1 + cb], sB[rb1 + cb + 4]);
            }
        }
    }

    // ---- epilogue ----
    // acc0: tile mr0, n-chunks ncb..ncb+3
    {
        const int q = mr0 * 16 + g;
        if (q < QN) {
            float* o = outb + (size_t)q * NPIX + p0 + ncb * 8 + i4 * 2;
            #pragma unroll
            for (int j = 0; j < 4; j++)
                *reinterpret_cast<float2*>(o + j * 8) = make_float2(acc0[j][0], acc0[j][1]);
        }
        const int q2 = q + 8;
        if (q2 < QN) {
            float* o2 = outb + (size_t)q2 * NPIX + p0 + ncb * 8 + i4 * 2;
            #pragma unroll
            for (int j = 0; j < 4; j++)
                *reinterpret_cast<float2*>(o2 + j * 8) = make_float2(acc0[j][2], acc0[j][3]);
        }
    }
    // acc1: dual -> tile mr1 same ncs; single -> tile 12, n-chunks 4..7
    {
        const int mrx = dual ? mr1 : mr0;
        const int ncx = dual ? ncb : 4;
        const int q = mrx * 16 + g;
        if (q < QN) {
            float* o = outb + (size_t)q * NPIX + p0 + ncx * 8 + i4 * 2;
            #pragma unroll
            for (int j = 0; j < 4; j++)
                *reinterpret_cast<float2*>(o + j * 8) = make_float2(acc1[j][0], acc1[j][1]);
        }
        const int q2 = q + 8;
        if (q2 < QN) {
            float* o2 = outb + (size_t)q2 * NPIX + p0 + ncx * 8 + i4 * 2;
            #pragma unroll
            for (int j = 0; j < 4; j++)
                *reinterpret_cast<float2*>(o2 + j * 8) = make_float2(acc1[j][2], acc1[j][3]);
        }
    }
}

// ---------------------------------------------------------------------------
extern "C" void kernel_launch(void* const* d_in, const int* in_sizes, int n_in,
                              void* d_out, int out_size)
{
    const float* queries = (const float*)d_in[0];  // (4, 200, 256)
    const float* mf      = (const float*)d_in[1];  // (4, 256, 256, 256)
    const float* w1      = (const float*)d_in[2];
    const float* b1      = (const float*)d_in[3];
    const float* w2      = (const float*)d_in[4];
    const float* b2      = (const float*)d_in[5];
    float* out = (float*)d_out;                    // (4, 200, 256, 256)

    float* hbuf;  cudaGetSymbolAddress((void**)&hbuf,  g_h);
    float* mebuf; cudaGetSymbolAddress((void**)&mebuf, g_me);

    const int smem = PTILE * BSTRIDE * (int)sizeof(uint32_t);   // 33792 B
    cudaFuncSetAttribute(gemm_kernel, cudaFuncAttributeMaxDynamicSharedMemorySize, smem);

    layer_kernel<true ><<<dim3(NROW / 32, HID / 32), 128>>>(queries, w1, b1, hbuf);
    layer_kernel<false><<<dim3(NROW / 32, HID / 32), 128>>>(hbuf,    w2, b2, mebuf);
    pack_kernel<<<NB * MROWS, 512>>>();
    gemm_kernel<<<dim3(NPIX / PTILE, NB), GTHREADS, smem>>>(mf, out);
}

// round 10
// speedup vs baseline: 1.5875x; 1.2145x over previous
#include <cuda_runtime.h>
#include <cuda_fp16.h>
#include <cstdint>

#define HID  256
#define QN   200
#define NPIX (256 * 256)
#define NB   4
#define NROW (NB * QN)    // 800 merged (b,q) rows

#define MROWS   13        // ceil(200/16) query row-tiles of 16
#define KSTEPS  16        // 256 / 16
#define PTILE   64        // pixels per GEMM CTA
#define BSTRIDE 132       // smem row stride in u32 (k-pairs), conflict-free
#define NWARP   13        // one warp per m-row tile (R7 shape)
#define GTHREADS (NWARP * 32)

// ---------------------------------------------------------------------------
// Device scratch (allocation-free)
// ---------------------------------------------------------------------------
__device__ float g_h [NROW * HID];                          // hidden fp32
__device__ float g_me[NROW * HID];                          // mask_embed fp32
__device__ uint4 g_AH[NB * MROWS * KSTEPS * 32];            // A fragments (fp16)

// ---------------------------------------------------------------------------
// mma.sync m16n8k16 fp16 in / fp32 accum + ldmatrix (baseline PTX, sm_100 OK)
// ---------------------------------------------------------------------------
__device__ __forceinline__ void mma_f16(float* d, uint4 a, uint32_t b0, uint32_t b1) {
    asm volatile(
        "mma.sync.aligned.m16n8k16.row.col.f32.f16.f16.f32 "
        "{%0,%1,%2,%3}, {%4,%5,%6,%7}, {%8,%9}, {%0,%1,%2,%3};"
        : "+f"(d[0]), "+f"(d[1]), "+f"(d[2]), "+f"(d[3])
        : "r"(a.x), "r"(a.y), "r"(a.z), "r"(a.w), "r"(b0), "r"(b1));
}

__device__ __forceinline__ void ldsm_x4(uint32_t& r0, uint32_t& r1,
                                        uint32_t& r2, uint32_t& r3, uint32_t addr) {
    asm volatile("ldmatrix.sync.aligned.m8n8.x4.shared.b16 {%0,%1,%2,%3}, [%4];"
        : "=r"(r0), "=r"(r1), "=r"(r2), "=r"(r3) : "r"(addr));
}

__device__ __forceinline__ uint32_t pack_f16(float a, float b) {
    __half2 h = __floats2half2_rn(a, b);
    return *reinterpret_cast<uint32_t*>(&h);
}

// ---------------------------------------------------------------------------
// MLP layer kernel: C[r, n] = act( sum_k A[r,k] * W[n,k] + bias[n] )
// 32x32 tile, 128 threads, coalesced smem staging.
// grid = (NROW/32 = 25, HID/32 = 8)
// ---------------------------------------------------------------------------
template<bool RELU>
__global__ __launch_bounds__(128) void layer_kernel(
    const float* __restrict__ A, const float* __restrict__ W,
    const float* __restrict__ bias, float* __restrict__ C)
{
    __shared__ float sA[16][32];   // [k][row]
    __shared__ float sW[16][32];   // [k][col]

    const int tid = threadIdx.x;
    const int r0 = blockIdx.x * 32;
    const int n0 = blockIdx.y * 32;
    const int tr = tid & 7;        // row group: 4 rows
    const int tc = tid >> 3;       // col group: 2 cols (0..15)
    const int lrow = tid >> 2;     // 0..31: load row
    const int lj   = (tid & 3) * 4;

    float acc[4][2] = {};

    for (int kc = 0; kc < HID; kc += 16) {
        __syncthreads();
        float4 va = *reinterpret_cast<const float4*>(A + (size_t)(r0 + lrow) * HID + kc + lj);
        sA[lj+0][lrow] = va.x; sA[lj+1][lrow] = va.y;
        sA[lj+2][lrow] = va.z; sA[lj+3][lrow] = va.w;
        float4 vw = *reinterpret_cast<const float4*>(W + (size_t)(n0 + lrow) * HID + kc + lj);
        sW[lj+0][lrow] = vw.x; sW[lj+1][lrow] = vw.y;
        sW[lj+2][lrow] = vw.z; sW[lj+3][lrow] = vw.w;
        __syncthreads();

        #pragma unroll
        for (int k = 0; k < 16; k++) {
            float4 a = *reinterpret_cast<const float4*>(&sA[k][tr * 4]);
            float2 w = *reinterpret_cast<const float2*>(&sW[k][tc * 2]);
            acc[0][0] = fmaf(a.x, w.x, acc[0][0]); acc[0][1] = fmaf(a.x, w.y, acc[0][1]);
            acc[1][0] = fmaf(a.y, w.x, acc[1][0]); acc[1][1] = fmaf(a.y, w.y, acc[1][1]);
            acc[2][0] = fmaf(a.z, w.x, acc[2][0]); acc[2][1] = fmaf(a.z, w.y, acc[2][1]);
            acc[3][0] = fmaf(a.w, w.x, acc[3][0]); acc[3][1] = fmaf(a.w, w.y, acc[3][1]);
        }
    }

    const float b0 = bias[n0 + tc * 2];
    const float b1 = bias[n0 + tc * 2 + 1];
    #pragma unroll
    for (int r = 0; r < 4; r++) {
        float v0 = acc[r][0] + b0;
        float v1 = acc[r][1] + b1;
        if (RELU) { v0 = v0 > 0.f ? v0 : 0.f; v1 = v1 > 0.f ? v1 : 0.f; }
        *reinterpret_cast<float2*>(C + (size_t)(r0 + tr * 4 + r) * HID + n0 + tc * 2)
            = make_float2(v0, v1);
    }
}

// ---------------------------------------------------------------------------
// Pack mask_embed into per-lane A fragments (single fp16 rounding).
// A frag (m16n8k16): lane t (g=t/4, i=t%4) holds rows {mr*16+g, +8},
// cols {ks*16+2i, +1, +8, +9}.
// ---------------------------------------------------------------------------
__global__ __launch_bounds__(512) void pack_kernel()
{
    const int blk = blockIdx.x;              // b*MROWS + mr
    const int b   = blk / MROWS;
    const int mr  = blk % MROWS;
    const int ks  = threadIdx.x >> 5;        // 0..15
    const int lane = threadIdx.x & 31;
    const int g = lane >> 2, i4 = lane & 3;

    const int r0 = mr * 16 + g;
    const int r1 = r0 + 8;
    const int c0 = ks * 16 + i4 * 2;

    float v[2][4];
    #pragma unroll
    for (int rr = 0; rr < 2; rr++) {
        const int r = rr ? r1 : r0;
        #pragma unroll
        for (int cc = 0; cc < 4; cc++) {
            const int c = c0 + (cc >> 1) * 8 + (cc & 1);
            v[rr][cc] = (r < QN) ? g_me[(size_t)(b * QN + r) * HID + c] : 0.f;
        }
    }

    uint4 ah;
    ah.x = pack_f16(v[0][0], v[0][1]);
    ah.y = pack_f16(v[1][0], v[1][1]);
    ah.z = pack_f16(v[0][2], v[0][3]);
    ah.w = pack_f16(v[1][2], v[1][3]);

    g_AH[((size_t)(b * MROWS + mr) * KSTEPS + ks) * 32 + lane] = ah;
}

// ---------------------------------------------------------------------------
// GEMM: out[b,q,p] = sum_c me[b,q,c] * mf[b,c,p]
// R7 shape: CTA = 64-pixel stripe x all query rows; 13 warps, one m-tile
// each, rotated by blockIdx.x.  NEW: B fragments via ldmatrix.x4 —
// smem layout [pixel][kpair] IS the m8n8.b16 fragment layout, so each
// ldmatrix.x4 yields {b0,b1} for two n-chunks.  Inner loop per k-step:
// 1 LDG.128 + 4 LDSM + 8 HMMA (was 1 LDG + 16 LDS + 8 HMMA + addr ALU).
// ---------------------------------------------------------------------------
__global__ __launch_bounds__(GTHREADS) void gemm_kernel(
    const float* __restrict__ mf, float* __restrict__ out)
{
    extern __shared__ uint32_t sB[];               // [64 pixels][BSTRIDE kpairs]

    const int tid  = threadIdx.x;
    const int lane = tid & 31;
    const int w    = tid >> 5;
    const int g    = lane >> 2, i4 = lane & 3;

    const int p0 = blockIdx.x * PTILE;
    const int b  = blockIdx.y;

    const float* mfb  = mf  + (size_t)b * HID * NPIX;
    float*       outb = out + (size_t)b * QN  * NPIX;

    // ---- load + convert B tile: 64 pixels x 256 channels, fp32 -> fp16 ----
    for (int idx = tid; idx < 128 * 16; idx += GTHREADS) {
        const int cp  = idx >> 4;
        const int p4  = idx & 15;
        const float* r0 = mfb + (size_t)(2 * cp)     * NPIX + p0 + p4 * 4;
        const float* r1 = mfb + (size_t)(2 * cp + 1) * NPIX + p0 + p4 * 4;
        float4 v0 = *reinterpret_cast<const float4*>(r0);
        float4 v1 = *reinterpret_cast<const float4*>(r1);
        const float a0[4] = {v0.x, v0.y, v0.z, v0.w};
        const float a1[4] = {v1.x, v1.y, v1.z, v1.w};
        #pragma unroll
        for (int s = 0; s < 4; s++) {
            const int j = (s + p4) & 3;            // stagger -> fewer store conflicts
            sB[(uint32_t)(p4 * 4 + j) * BSTRIDE + cp] = pack_f16(a0[j], a1[j]);
        }
    }
    __syncthreads();

    // ---- compute: warp wp owns m-tile (w + bx) % 13 ----
    const int mr = (w + (int)blockIdx.x) % NWARP;

    float acc[8][4];
    #pragma unroll
    for (int n = 0; n < 8; n++)
        #pragma unroll
        for (int x = 0; x < 4; x++) acc[n][x] = 0.f;

    const uint4* pAH = g_AH + ((size_t)(b * MROWS + mr) * KSTEPS) * 32 + lane;

    // per-thread ldmatrix base address:
    // quad q8 = lane/8 selects matrix within x4: {b0 nc, b1 nc, b0 nc+1, b1 nc+1}
    // row = (q8>=2)*8 + lane%8 ; u32-col = (q8&1)*4
    const int q8 = lane >> 3;
    const int r8 = lane & 7;
    const uint32_t sB_addr = (uint32_t)__cvta_generic_to_shared(sB);
    const uint32_t lm_base = sB_addr +
        (uint32_t)((((q8 >> 1) * 8 + r8) * BSTRIDE + (q8 & 1) * 4) * 4);
    const uint32_t J_STRIDE = (uint32_t)(16 * BSTRIDE * 4);   // two n-chunks of rows

    #pragma unroll 4
    for (int ks = 0; ks < KSTEPS; ks++) {
        const uint4 ah = pAH[ks * 32];
        const uint32_t ka = lm_base + (uint32_t)(ks * 32);    // ks*8 u32 cols
        #pragma unroll
        for (int j = 0; j < 4; j++) {
            uint32_t b0, b1, b2, b3;
            ldsm_x4(b0, b1, b2, b3, ka + (uint32_t)j * J_STRIDE);
            mma_f16(acc[2 * j],     ah, b0, b1);
            mma_f16(acc[2 * j + 1], ah, b2, b3);
        }
    }

    // ---- epilogue: D frag (16x8) rows = queries, cols = pixel pairs ----
    {
        const int q = mr * 16 + g;
        if (q < QN) {
            float* o = outb + (size_t)q * NPIX + p0 + i4 * 2;
            #pragma unroll
            for (int nc = 0; nc < 8; nc++)
                *reinterpret_cast<float2*>(o + nc * 8) = make_float2(acc[nc][0], acc[nc][1]);
        }
        const int q2 = q + 8;
        if (q2 < QN) {
            float* o2 = outb + (size_t)q2 * NPIX + p0 + i4 * 2;
            #pragma unroll
            for (int nc = 0; nc < 8; nc++)
                *reinterpret_cast<float2*>(o2 + nc * 8) = make_float2(acc[nc][2], acc[nc][3]);
        }
    }
}

// ---------------------------------------------------------------------------
extern "C" void kernel_launch(void* const* d_in, const int* in_sizes, int n_in,
                              void* d_out, int out_size)
{
    const float* queries = (const float*)d_in[0];  // (4, 200, 256)
    const float* mf      = (const float*)d_in[1];  // (4, 256, 256, 256)
    const float* w1      = (const float*)d_in[2];
    const float* b1      = (const float*)d_in[3];
    const float* w2      = (const float*)d_in[4];
    const float* b2      = (const float*)d_in[5];
    float* out = (float*)d_out;                    // (4, 200, 256, 256)

    float* hbuf;  cudaGetSymbolAddress((void**)&hbuf,  g_h);
    float* mebuf; cudaGetSymbolAddress((void**)&mebuf, g_me);

    const int smem = PTILE * BSTRIDE * (int)sizeof(uint32_t);   // 33792 B
    cudaFuncSetAttribute(gemm_kernel, cudaFuncAttributeMaxDynamicSharedMemorySize, smem);

    layer_kernel<true ><<<dim3(NROW / 32, HID / 32), 128>>>(queries, w1, b1, hbuf);
    layer_kernel<false><<<dim3(NROW / 32, HID / 32), 128>>>(hbuf,    w2, b2, mebuf);
    pack_kernel<<<NB * MROWS, 512>>>();
    gemm_kernel<<<dim3(NPIX / PTILE, NB), GTHREADS, smem>>>(mf, out);
}